// round 10
// baseline (speedup 1.0000x reference)
#include <cuda_runtime.h>
#include <cuda_fp16.h>
#include <cstdint>

// ---------------- problem constants ----------------
#define HS 112
#define WS 112
#define CI 128
#define CO 256
#define NIMG 32
#define TYN 56
#define TXN 56
#define NT_IMG (TYN * TXN)          // 3136 winograd tiles per image
#define MTILES (NIMG * NT_IMG)      // 100352 GEMM rows
#define VPLANE ((size_t)MTILES * CI)
#define UPLANE (CO * CI)

// ---------------- GEMM tiling ----------------
#define BMT 64                  // winograd tiles per CTA
#define BN 64                   // out channels per CTA
#define STAGE_B 8192            // A-only stage: 64 rows x 128B
#define NSTG 8
#define PF 6                    // prefetch depth
#define SMEM_TOTAL (NSTG * STAGE_B)   // 65536

// static device scratch
__device__ __align__(16) __half g_V[16 * VPLANE];      // 411 MB transformed input
__device__ __align__(16) unsigned char g_U2[1 << 20];  // 1 MB fragment-major filters

__device__ __forceinline__ uint32_t smem_u32(const void* p) {
    uint32_t a;
    asm("{ .reg .u64 t; cvta.to.shared.u64 t, %1; cvt.u32.u64 %0, t; }" : "=r"(a) : "l"(p));
    return a;
}

// fragment-major U address for scalar (c, n, k):
//   byte = (((c*4 + n>>6)*2 + (n>>5)&1)*2 + k>>6)*4096 + ((k>>4)&3)*1024 + ((n>>4)&1)*512
//        + l*16 + ((n>>3)&1)*8 + ((k>>3)&1)*4 + (k&1)*2 ,  l = ((n&7)<<2)|((k>>1)&3)
__device__ __forceinline__ uint32_t u2_byte(int c, int n, int k) {
    uint32_t l     = (uint32_t)(((n & 7) << 2) | ((k >> 1) & 3));
    uint32_t idx16 = ((((((uint32_t)c * 4 + (n >> 6)) * 2 + ((n >> 5) & 1)) * 2
                        + (k >> 6)) * 4 + ((k >> 4) & 3)) * 2 + ((n >> 4) & 1));
    return idx16 * 512 + l * 16 + ((n >> 3) & 1) * 8 + ((k >> 3) & 1) * 4 + (k & 1) * 2;
}

// ---------------- U = G sign(g) G^T, scattered to fragment-major ----------------
__global__ void wino_filter_kernel(const float* __restrict__ wsrc) {
    const int k = threadIdx.x;    // ci 0..127
    const int n = blockIdx.x;     // co 0..255
    float s[3][3];
#pragma unroll
    for (int ky = 0; ky < 3; ky++)
#pragma unroll
        for (int kx = 0; kx < 3; kx++) {
            float v = wsrc[((size_t)(ky * 3 + kx) * CI + k) * CO + n];
            s[ky][kx] = (float)((v > 0.f) - (v < 0.f));
        }
    float t[4][3];
#pragma unroll
    for (int j = 0; j < 3; j++) {
        t[0][j] = s[0][j];
        t[1][j] = 0.5f * (s[0][j] + s[1][j] + s[2][j]);
        t[2][j] = 0.5f * (s[0][j] - s[1][j] + s[2][j]);
        t[3][j] = s[2][j];
    }
#pragma unroll
    for (int i = 0; i < 4; i++) {
        float u[4];
        u[0] = t[i][0];
        u[1] = 0.5f * (t[i][0] + t[i][1] + t[i][2]);
        u[2] = 0.5f * (t[i][0] - t[i][1] + t[i][2]);
        u[3] = t[i][2];
#pragma unroll
        for (int j = 0; j < 4; j++)
            *reinterpret_cast<__half*>(g_U2 + u2_byte(i * 4 + j, n, k)) = __float2half(u[j]);
    }
}

// ---------------- V = B^T d B ----------------
__global__ __launch_bounds__(256)
void wino_input_kernel(const float* __restrict__ x) {
    const int w    = threadIdx.x >> 5;
    const int lane = threadIdx.x & 31;
    const int tile = blockIdx.x * 4 + (w >> 1);
    const int ch   = (w & 1) * 64 + lane * 2;

    const int nimg = tile / NT_IMG;
    const int rr   = tile - nimg * NT_IMG;
    const int ty   = rr / TXN;
    const int tx   = rr - ty * TXN;

    float a[4][4], b[4][4];
#pragma unroll
    for (int i = 0; i < 4; i++) {
        const int ih = 2 * ty - 1 + i;
#pragma unroll
        for (int j = 0; j < 4; j++) {
            const int iw = 2 * tx - 1 + j;
            float2 v = make_float2(0.f, 0.f);
            if ((unsigned)ih < (unsigned)HS && (unsigned)iw < (unsigned)WS)
                v = *reinterpret_cast<const float2*>(
                    x + (((size_t)nimg * HS + ih) * WS + iw) * CI + ch);
            a[i][j] = v.x; b[i][j] = v.y;
        }
    }
    float ma[4][4], mb[4][4];
#pragma unroll
    for (int j = 0; j < 4; j++) {
        ma[0][j] = a[0][j] - a[2][j];  mb[0][j] = b[0][j] - b[2][j];
        ma[1][j] = a[1][j] + a[2][j];  mb[1][j] = b[1][j] + b[2][j];
        ma[2][j] = a[2][j] - a[1][j];  mb[2][j] = b[2][j] - b[1][j];
        ma[3][j] = a[1][j] - a[3][j];  mb[3][j] = b[1][j] - b[3][j];
    }
    __half* dst = g_V + (size_t)tile * CI + ch;
#pragma unroll
    for (int i = 0; i < 4; i++) {
        float va[4], vb[4];
        va[0] = ma[i][0] - ma[i][2];  vb[0] = mb[i][0] - mb[i][2];
        va[1] = ma[i][1] + ma[i][2];  vb[1] = mb[i][1] + mb[i][2];
        va[2] = ma[i][2] - ma[i][1];  vb[2] = mb[i][2] - mb[i][1];
        va[3] = ma[i][1] - ma[i][3];  vb[3] = mb[i][1] - mb[i][3];
#pragma unroll
        for (int j = 0; j < 4; j++)
            *reinterpret_cast<__half2*>(dst + (size_t)(i * 4 + j) * VPLANE) =
                __floats2half2_rn(va[j], vb[j]);
    }
}

// ---------------- GEMM: A via smem/ldmatrix, B via fragment LDG.128 ----------------
extern __shared__ __align__(1024) unsigned char smem_raw[];

__global__ __launch_bounds__(256, 2)
void wino_gemm_kernel(float* __restrict__ out) {
    const int tid = threadIdx.x;
    const int l   = tid & 31;
    const int wid = tid >> 5;
    const int warpM = wid & 3;     // 4 warps x 16 tile-rows
    const int warpN = wid >> 2;    // 2 warps x 32 cols
    const uint32_t smem = smem_u32(smem_raw);

    // ---- A cp.async loader: row lr (0..63), 32B chunk lc (0..3) ----
    const int lr = tid >> 2;
    const int lc = tid & 3;
    const uint32_t dst0 = ((uint32_t)(lr * 128 + lc * 32)) ^ ((uint32_t)(lr & 7) << 4);
    const uint32_t dst1 = dst0 ^ 16u;
    const __half* aV = g_V + ((size_t)blockIdx.y * BMT + lr) * CI + lc * 16;

    // ---- A ldmatrix address components ----
    const uint32_t a_rb = (uint32_t)((warpM * 16 + (l & 15)) * 128);
    const uint32_t a_sw = (uint32_t)(l & 7) << 4;
    const uint32_t a_cb = (uint32_t)(l >> 4) * 16;

    float oacc[4][16];
#pragma unroll
    for (int p = 0; p < 4; p++)
#pragma unroll
        for (int q = 0; q < 16; q++) oacc[p][q] = 0.f;

    auto issue = [&](int cs) {
        const int c  = cs >> 1;
        const int kt = cs & 1;
        const uint32_t sb = smem + (uint32_t)(cs & (NSTG - 1)) * STAGE_B;
        const __half* as = aV + (size_t)c * VPLANE + kt * 64;
        asm volatile("cp.async.cg.shared.global [%0], [%1], 16;" :: "r"(sb + dst0), "l"(as));
        asm volatile("cp.async.cg.shared.global [%0], [%1], 16;" :: "r"(sb + dst1), "l"(as + 8));
    };

#pragma unroll
    for (int cs = 0; cs < PF; cs++) {
        issue(cs);
        asm volatile("cp.async.commit_group;" ::: "memory");
    }

    const int AT[2][4] = {{1, 1, 1, 0}, {0, 1, -1, -1}};

#pragma unroll
    for (int c = 0; c < 16; c++) {
        float tacc[16];
#pragma unroll
        for (int q = 0; q < 16; q++) tacc[q] = 0.f;

#pragma unroll
        for (int kt = 0; kt < 2; kt++) {
            const int cs = c * 2 + kt;
            asm volatile("cp.async.wait_group %0;" :: "n"(PF - 1) : "memory");
            __syncthreads();
            if (cs + PF < 32) issue(cs + PF);
            asm volatile("cp.async.commit_group;" ::: "memory");

            const uint32_t sb = smem + (uint32_t)(cs & (NSTG - 1)) * STAGE_B;
            // B fragment pointer: outer stride 4096B (FIXED), kk stride 1024B, ntp stride 512B
            const unsigned char* bp = g_U2
                + (size_t)(((c * 4 + blockIdx.x) * 2 + warpN) * 2 + kt) * 4096
                + (size_t)l * 16;
#pragma unroll
            for (int kk = 0; kk < 4; kk++) {
                uint4 bf0 = *reinterpret_cast<const uint4*>(bp + kk * 1024);
                uint4 bf1 = *reinterpret_cast<const uint4*>(bp + kk * 1024 + 512);
                uint32_t a[4];
                {
                    const uint32_t addr = sb + a_rb + ((a_cb + kk * 32) ^ a_sw);
                    asm volatile("ldmatrix.sync.aligned.m8n8.x4.shared.b16 {%0,%1,%2,%3}, [%4];"
                                 : "=r"(a[0]), "=r"(a[1]), "=r"(a[2]), "=r"(a[3]) : "r"(addr));
                }
                // nt = ntp*2 + nlo ; nlo=0 -> f.x/f.y, nlo=1 -> f.z/f.w
#pragma unroll
                for (int ntp = 0; ntp < 2; ntp++) {
                    const uint4 f = ntp ? bf1 : bf0;
                    asm volatile(
                        "mma.sync.aligned.m16n8k16.row.col.f32.f16.f16.f32 "
                        "{%0,%1,%2,%3}, {%4,%5,%6,%7}, {%8,%9}, {%0,%1,%2,%3};"
                        : "+f"(tacc[ntp * 8 + 0]), "+f"(tacc[ntp * 8 + 1]),
                          "+f"(tacc[ntp * 8 + 2]), "+f"(tacc[ntp * 8 + 3])
                        : "r"(a[0]), "r"(a[1]), "r"(a[2]), "r"(a[3]),
                          "r"(f.x), "r"(f.y));
                    asm volatile(
                        "mma.sync.aligned.m16n8k16.row.col.f32.f16.f16.f32 "
                        "{%0,%1,%2,%3}, {%4,%5,%6,%7}, {%8,%9}, {%0,%1,%2,%3};"
                        : "+f"(tacc[ntp * 8 + 4]), "+f"(tacc[ntp * 8 + 5]),
                          "+f"(tacc[ntp * 8 + 6]), "+f"(tacc[ntp * 8 + 7])
                        : "r"(a[0]), "r"(a[1]), "r"(a[2]), "r"(a[3]),
                          "r"(f.z), "r"(f.w));
                }
            }
        }

        // fused output transform
        const int cy = c >> 2, cx = c & 3;
#pragma unroll
        for (int py = 0; py < 2; py++)
#pragma unroll
            for (int px = 0; px < 2; px++) {
                const int alpha = AT[py][cy] * AT[px][cx];
                if (alpha == 1) {
#pragma unroll
                    for (int q = 0; q < 16; q++) oacc[py * 2 + px][q] += tacc[q];
                } else if (alpha == -1) {
#pragma unroll
                    for (int q = 0; q < 16; q++) oacc[py * 2 + px][q] -= tacc[q];
                }
            }
    }

    // ---- store: n = warpN*32 + ntp*16 + nlo*8 + (l&3)*2 ; rows via rsel (+8) ----
    const int colb = blockIdx.x * BN + warpN * 32 + (l & 3) * 2;
#pragma unroll
    for (int rsel = 0; rsel < 2; rsel++) {
        const int t = blockIdx.y * BMT + warpM * 16 + (l >> 2) + rsel * 8;
        const int nimg = t / NT_IMG;
        const int rr   = t - nimg * NT_IMG;
        const int ty   = rr / TXN;
        const int tx   = rr - ty * TXN;
#pragma unroll
        for (int py = 0; py < 2; py++)
#pragma unroll
            for (int px = 0; px < 2; px++) {
                float* o = out + (((size_t)nimg * HS + 2 * ty + py) * WS + (2 * tx + px)) * CO + colb;
                const int p = py * 2 + px;
#pragma unroll
                for (int ntp = 0; ntp < 2; ntp++)
#pragma unroll
                    for (int nlo = 0; nlo < 2; nlo++) {
                        const int q = ntp * 8 + nlo * 4 + rsel * 2;
                        *reinterpret_cast<float2*>(o + ntp * 16 + nlo * 8) =
                            make_float2(oacc[p][q], oacc[p][q + 1]);
                    }
            }
    }
}

// ---------------- launch ----------------
extern "C" void kernel_launch(void* const* d_in, const int* in_sizes, int n_in,
                              void* d_out, int out_size) {
    const float* x = (const float*)d_in[0];
    const float* w = (const float*)d_in[1];
    float* out = (float*)d_out;

    static bool init = false;
    if (!init) {
        cudaFuncSetAttribute(wino_gemm_kernel,
                             cudaFuncAttributeMaxDynamicSharedMemorySize, SMEM_TOTAL);
        init = true;
    }

    wino_filter_kernel<<<CO, CI>>>(w);
    wino_input_kernel<<<MTILES / 4, 256>>>(x);
    wino_gemm_kernel<<<dim3(CO / BN, MTILES / BMT), 256, SMEM_TOTAL>>>(out);   // (4, 1568)
}

// round 11
// speedup vs baseline: 1.2529x; 1.2529x over previous
#include <cuda_runtime.h>
#include <cuda_fp16.h>
#include <cstdint>

// ---------------- problem constants ----------------
#define HS 112
#define WS 112
#define CI 128
#define CO 256
#define NIMG 32
#define TYN 56
#define TXN 56
#define NT_IMG (TYN * TXN)          // 3136 winograd tiles per image
#define MTILES (NIMG * NT_IMG)      // 100352 GEMM rows
#define VPLANE ((size_t)MTILES * CI)
#define UPLANE (CO * CI)

// ---------------- GEMM tiling ----------------
#define BMT 64                  // winograd tiles per CTA
#define BN 64                   // out channels per CTA
#define STAGE_B 16384           // A 8KB + B 8KB per (coord, k64) chunk
#define NSTG 6
#define INFLT 5                 // stages in flight
#define SMEM_TOTAL (NSTG * STAGE_B)   // 98304

// static device scratch
__device__ __align__(16) __half g_V[16 * VPLANE];     // 411 MB transformed input
__device__ __align__(16) __half g_U[16 * UPLANE];     // 1 MB transformed binary filters

__device__ __forceinline__ uint32_t smem_u32(const void* p) {
    uint32_t a;
    asm("{ .reg .u64 t; cvta.to.shared.u64 t, %1; cvt.u32.u64 %0, t; }" : "=r"(a) : "l"(p));
    return a;
}

// ---------------- U = G sign(g) G^T  (exact in fp16) ----------------
__global__ void wino_filter_kernel(const float* __restrict__ wsrc) {
    const int k = threadIdx.x;    // 0..127 (ci)
    const int n = blockIdx.x;     // 0..255 (co)
    float s[3][3];
#pragma unroll
    for (int ky = 0; ky < 3; ky++)
#pragma unroll
        for (int kx = 0; kx < 3; kx++) {
            float v = wsrc[((size_t)(ky * 3 + kx) * CI + k) * CO + n];
            s[ky][kx] = (float)((v > 0.f) - (v < 0.f));
        }
    float t[4][3];
#pragma unroll
    for (int j = 0; j < 3; j++) {
        t[0][j] = s[0][j];
        t[1][j] = 0.5f * (s[0][j] + s[1][j] + s[2][j]);
        t[2][j] = 0.5f * (s[0][j] - s[1][j] + s[2][j]);
        t[3][j] = s[2][j];
    }
#pragma unroll
    for (int i = 0; i < 4; i++) {
        float u0 = t[i][0];
        float u1 = 0.5f * (t[i][0] + t[i][1] + t[i][2]);
        float u2 = 0.5f * (t[i][0] - t[i][1] + t[i][2]);
        float u3 = t[i][2];
        g_U[(size_t)(i * 4 + 0) * UPLANE + n * CI + k] = __float2half(u0);
        g_U[(size_t)(i * 4 + 1) * UPLANE + n * CI + k] = __float2half(u1);
        g_U[(size_t)(i * 4 + 2) * UPLANE + n * CI + k] = __float2half(u2);
        g_U[(size_t)(i * 4 + 3) * UPLANE + n * CI + k] = __float2half(u3);
    }
}

// ---------------- V = B^T d B  per tile, per channel pair ----------------
__global__ __launch_bounds__(256)
void wino_input_kernel(const float* __restrict__ x) {
    const int w    = threadIdx.x >> 5;
    const int lane = threadIdx.x & 31;
    const int tile = blockIdx.x * 4 + (w >> 1);
    const int ch   = (w & 1) * 64 + lane * 2;

    const int nimg = tile / NT_IMG;
    const int rr   = tile - nimg * NT_IMG;
    const int ty   = rr / TXN;
    const int tx   = rr - ty * TXN;

    float a[4][4], b[4][4];
#pragma unroll
    for (int i = 0; i < 4; i++) {
        const int ih = 2 * ty - 1 + i;
#pragma unroll
        for (int j = 0; j < 4; j++) {
            const int iw = 2 * tx - 1 + j;
            float2 v = make_float2(0.f, 0.f);
            if ((unsigned)ih < (unsigned)HS && (unsigned)iw < (unsigned)WS)
                v = *reinterpret_cast<const float2*>(
                    x + (((size_t)nimg * HS + ih) * WS + iw) * CI + ch);
            a[i][j] = v.x; b[i][j] = v.y;
        }
    }
    float ma[4][4], mb[4][4];
#pragma unroll
    for (int j = 0; j < 4; j++) {
        ma[0][j] = a[0][j] - a[2][j];  mb[0][j] = b[0][j] - b[2][j];
        ma[1][j] = a[1][j] + a[2][j];  mb[1][j] = b[1][j] + b[2][j];
        ma[2][j] = a[2][j] - a[1][j];  mb[2][j] = b[2][j] - b[1][j];
        ma[3][j] = a[1][j] - a[3][j];  mb[3][j] = b[1][j] - b[3][j];
    }
    __half* dst = g_V + (size_t)tile * CI + ch;
#pragma unroll
    for (int i = 0; i < 4; i++) {
        float va[4], vb[4];
        va[0] = ma[i][0] - ma[i][2];  vb[0] = mb[i][0] - mb[i][2];
        va[1] = ma[i][1] + ma[i][2];  vb[1] = mb[i][1] + mb[i][2];
        va[2] = ma[i][2] - ma[i][1];  vb[2] = mb[i][2] - mb[i][1];
        va[3] = ma[i][1] - ma[i][3];  vb[3] = mb[i][1] - mb[i][3];
#pragma unroll
        for (int j = 0; j < 4; j++)
            *reinterpret_cast<__half2*>(dst + (size_t)(i * 4 + j) * VPLANE) =
                __floats2half2_rn(va[j], vb[j]);
    }
}

// ---------------- GEMM over 16 coords with fused output transform ----------------
extern __shared__ __align__(1024) unsigned char smem_raw[];

__global__ __launch_bounds__(256, 2)
void wino_gemm_kernel(float* __restrict__ out) {
    const int tid = threadIdx.x;
    const int l   = tid & 31;
    const int wid = tid >> 5;
    const int warpM = wid & 3;     // 4 warps x 16 tile-rows
    const int warpN = wid >> 2;    // 2 warps x 32 cols
    const uint32_t smem = smem_u32(smem_raw);

    // ---- cp.async loader mapping: row lr (0..63), 32B chunk lc (0..3) ----
    const int lr = tid >> 2;
    const int lc = tid & 3;
    const uint32_t dst0 = ((uint32_t)(lr * 128 + lc * 32)) ^ ((uint32_t)(lr & 7) << 4);
    const uint32_t dst1 = dst0 ^ 16u;
    const __half* aV = g_V + ((size_t)blockIdx.y * BMT + lr) * CI + lc * 16;
    const __half* bU = g_U + ((size_t)blockIdx.x * BN  + lr) * CI + lc * 16;

    // ---- ldmatrix address components ----
    const uint32_t a_rb = (uint32_t)((warpM * 16 + (l & 15)) * 128);
    const uint32_t a_sw = (uint32_t)(l & 7) << 4;
    const uint32_t a_cb = (uint32_t)(l >> 4) * 16;
    uint32_t b_rb[2], b_sw[2];
#pragma unroll
    for (int ntp = 0; ntp < 2; ntp++) {
        int r = warpN * 32 + ntp * 16 + ((l >> 4) << 3) + (l & 7);
        b_rb[ntp] = 8192u + (uint32_t)(r * 128);
        b_sw[ntp] = (uint32_t)(r & 7) << 4;
    }
    const uint32_t b_cb = (uint32_t)((l >> 3) & 1) * 16;

    float oacc[4][16];
#pragma unroll
    for (int p = 0; p < 4; p++)
#pragma unroll
        for (int q = 0; q < 16; q++) oacc[p][q] = 0.f;

    auto issue = [&](int cs) {
        const int c  = cs >> 1;
        const int kt = cs & 1;
        const uint32_t sb = smem + (uint32_t)(cs % NSTG) * STAGE_B;
        const __half* as = aV + (size_t)c * VPLANE + kt * 64;
        asm volatile("cp.async.cg.shared.global [%0], [%1], 16;" :: "r"(sb + dst0), "l"(as));
        asm volatile("cp.async.cg.shared.global [%0], [%1], 16;" :: "r"(sb + dst1), "l"(as + 8));
        const __half* bs = bU + (size_t)c * UPLANE + kt * 64;
        asm volatile("cp.async.cg.shared.global [%0], [%1], 16;" :: "r"(sb + 8192 + dst0), "l"(bs));
        asm volatile("cp.async.cg.shared.global [%0], [%1], 16;" :: "r"(sb + 8192 + dst1), "l"(bs + 8));
    };

#pragma unroll
    for (int cs = 0; cs < INFLT; cs++) {
        issue(cs);
        asm volatile("cp.async.commit_group;" ::: "memory");
    }

    const int AT[2][4] = {{1, 1, 1, 0}, {0, 1, -1, -1}};

#pragma unroll
    for (int c = 0; c < 16; c++) {
        float tacc[16];
#pragma unroll
        for (int q = 0; q < 16; q++) tacc[q] = 0.f;

#pragma unroll
        for (int kt = 0; kt < 2; kt++) {
            const int cs = c * 2 + kt;
            asm volatile("cp.async.wait_group %0;" :: "n"(INFLT - 1) : "memory");
            __syncthreads();
            if (cs + INFLT < 32) issue(cs + INFLT);
            asm volatile("cp.async.commit_group;" ::: "memory");

            const uint32_t sb = smem + (uint32_t)(cs % NSTG) * STAGE_B;
#pragma unroll
            for (int kk = 0; kk < 4; kk++) {
                uint32_t a[4], b[2][4];
                {
                    const uint32_t addr = sb + a_rb + ((a_cb + kk * 32) ^ a_sw);
                    asm volatile("ldmatrix.sync.aligned.m8n8.x4.shared.b16 {%0,%1,%2,%3}, [%4];"
                                 : "=r"(a[0]), "=r"(a[1]), "=r"(a[2]), "=r"(a[3]) : "r"(addr));
                }
#pragma unroll
                for (int ntp = 0; ntp < 2; ntp++) {
                    const uint32_t addr = sb + b_rb[ntp] + ((b_cb + kk * 32) ^ b_sw[ntp]);
                    asm volatile("ldmatrix.sync.aligned.m8n8.x4.shared.b16 {%0,%1,%2,%3}, [%4];"
                                 : "=r"(b[ntp][0]), "=r"(b[ntp][1]), "=r"(b[ntp][2]), "=r"(b[ntp][3])
                                 : "r"(addr));
                }
#pragma unroll
                for (int nt = 0; nt < 4; nt++) {
                    const uint32_t b0 = b[nt >> 1][(nt & 1) * 2];
                    const uint32_t b1 = b[nt >> 1][(nt & 1) * 2 + 1];
                    asm volatile(
                        "mma.sync.aligned.m16n8k16.row.col.f32.f16.f16.f32 "
                        "{%0,%1,%2,%3}, {%4,%5,%6,%7}, {%8,%9}, {%0,%1,%2,%3};"
                        : "+f"(tacc[nt * 4 + 0]), "+f"(tacc[nt * 4 + 1]),
                          "+f"(tacc[nt * 4 + 2]), "+f"(tacc[nt * 4 + 3])
                        : "r"(a[0]), "r"(a[1]), "r"(a[2]), "r"(a[3]), "r"(b0), "r"(b1));
                }
            }
        }

        // fused output transform: out[py][px] += AT[py][cy]*AT[px][cx] * M_c
        const int cy = c >> 2, cx = c & 3;
#pragma unroll
        for (int py = 0; py < 2; py++)
#pragma unroll
            for (int px = 0; px < 2; px++) {
                const int alpha = AT[py][cy] * AT[px][cx];
                if (alpha == 1) {
#pragma unroll
                    for (int q = 0; q < 16; q++) oacc[py * 2 + px][q] += tacc[q];
                } else if (alpha == -1) {
#pragma unroll
                    for (int q = 0; q < 16; q++) oacc[py * 2 + px][q] -= tacc[q];
                }
            }
    }

    // ---- store: each thread covers 2 tile-rows x 4 n-blocks x 4 pixels ----
    const int colb = blockIdx.x * BN + warpN * 32 + (l & 3) * 2;
#pragma unroll
    for (int rsel = 0; rsel < 2; rsel++) {
        const int t = blockIdx.y * BMT + warpM * 16 + (l >> 2) + rsel * 8;
        const int nimg = t / NT_IMG;
        const int rr   = t - nimg * NT_IMG;
        const int ty   = rr / TXN;
        const int tx   = rr - ty * TXN;
#pragma unroll
        for (int py = 0; py < 2; py++)
#pragma unroll
            for (int px = 0; px < 2; px++) {
                float* o = out + (((size_t)nimg * HS + 2 * ty + py) * WS + (2 * tx + px)) * CO + colb;
                const int p = py * 2 + px;
#pragma unroll
                for (int nt = 0; nt < 4; nt++)
                    *reinterpret_cast<float2*>(o + nt * 8) =
                        make_float2(oacc[p][nt * 4 + rsel * 2], oacc[p][nt * 4 + rsel * 2 + 1]);
            }
    }
}

// ---------------- launch ----------------
extern "C" void kernel_launch(void* const* d_in, const int* in_sizes, int n_in,
                              void* d_out, int out_size) {
    const float* x = (const float*)d_in[0];   // (32,112,112,128) fp32 NHWC
    const float* w = (const float*)d_in[1];   // (3,3,128,256) fp32 HWIO
    float* out = (float*)d_out;               // (32,112,112,256) fp32

    static bool init = false;
    if (!init) {
        cudaFuncSetAttribute(wino_gemm_kernel,
                             cudaFuncAttributeMaxDynamicSharedMemorySize, SMEM_TOTAL);
        init = true;
    }

    wino_filter_kernel<<<CO, CI>>>(w);
    wino_input_kernel<<<MTILES / 4, 256>>>(x);
    wino_gemm_kernel<<<dim3(CO / BN, MTILES / BMT), 256, SMEM_TOTAL>>>(out);   // (4, 1568)
}